// round 13
// baseline (speedup 1.0000x reference)
#include <cuda_runtime.h>
#include <math.h>
#include <stdint.h>

// FootAndBall ball-detection post-process — ONE kernel (detect + cheap tail).
//  in : [16, 2, 540, 960] fp32 logits
//  out: [16, 100, 5] fp32 (x1,y1,x2,y2,score), score desc (idx asc on ties).
//
//  Phase 1 (all 720 blocks): d = x1-x0 (NMS on d == NMS on softmax prob,
//    monotone). Software-pipelined float4 streaming NMS (groups of 4 rows,
//    double buffered). Candidates -> block smem queue + smem histogram;
//    block-local top-100 cut filters before ONE contiguous per-batch flush.
//    Global top-100 ⊆ union of block-local top-100s; queue overflow falls
//    back to direct unfiltered append (superset -> correct).
//  Phase 2 (last-arriving block per batch, 16 of 720): strided-loop select
//    over the filtered candidates (smem histogram + log-parallel cut +
//    collect + exact (p desc, idx asc) rank + box write + state reset).
//    Tail uses NO register arrays: R12's 40-reg burst pushed the kernel to
//    127 regs -> 2 blocks/SM and slowed the streaming phase 2x. Tail is
//    loops; __launch_bounds__(256,3) caps regs at ~85 -> 3 blocks/SM.
//  __device__ globals start zero-initialized; the tail restores zeros.

#define BB   16
#define HH   540
#define WW   960
#define HWSZ (HH * WW)
#define KK   100

#define NT    256                 // threads per block (8 warps)
#define RPB   12                  // rows per block; 540 = 45 * 12
#define NBY   45                  // blocks per batch
#define QC    2048                // block smem queue entries (16 KB)
#define HB    4096                // histogram bins (top 12 flipped bits)
#define CAP   2048                // tail survivor capacity
#define CAPG  65536               // per-batch global candidate capacity

__device__ int    g_cnt [BB];
__device__ int    g_done[BB];
__device__ float2 g_cand[BB][CAPG];

// ---------------------------------------------------------------------------
// Exact softmax channel-1 prob from d = fl(x1-x0). Matches jax.nn.softmax:
// one exp arg is exactly 0 and fl(x0-x1) == -d exactly. (rel_err ~1e-12.)
// ---------------------------------------------------------------------------
__device__ __forceinline__ float prob_from_d(float d) {
#ifdef __FAST_MATH__
    double dd = (double)d;
    double p = (d >= 0.0f) ? (1.0 / (exp(-dd) + 1.0))
                           : (exp(dd) / (exp(dd) + 1.0));
    return (float)p;
#else
    if (d >= 0.0f) { float e0 = expf(-d); return 1.0f / (e0 + 1.0f); }
    else           { float e1 = expf(d);  return e1 / (1.0f + e1);  }
#endif
}

// Order-preserving bit flip: float compare == unsigned compare after flip.
__device__ __forceinline__ unsigned fflip(float f) {
    unsigned u = __float_as_uint(f);
    return u ^ (((unsigned)((int)u >> 31)) | 0x80000000u);
}

// ---------------------------------------------------------------------------
// Log-parallel cut over a 4096-bin smem histogram, 256 threads.
// *s_cut = flipped-bits threshold with count(>= thr) >= KK (0 if total < KK).
// Caller zeroes *s_cut + syncs before; must sync after.
// ---------------------------------------------------------------------------
__device__ __forceinline__ void cut_scan256(const int* __restrict__ hist,
                                            int* __restrict__ s_wtot,
                                            unsigned* __restrict__ s_cut,
                                            int t) {
    const int lane = t & 31;
    const int w    = t >> 5;
    const int seg  = 255 - t;                // descending bin order
    int val = 0;
    const int4* h4 = (const int4*)(hist + seg * 16);
    #pragma unroll
    for (int j = 0; j < 4; j++) { int4 a = h4[j]; val += a.x + a.y + a.z + a.w; }

    int incl = val;
    #pragma unroll
    for (int sh = 1; sh < 32; sh <<= 1) {
        int n = __shfl_up_sync(0xffffffffu, incl, sh);
        if (lane >= sh) incl += n;
    }
    if (lane == 31) s_wtot[w] = incl;
    __syncthreads();
    if (t < 8) {
        int v = s_wtot[t];
        int inc = v;
        #pragma unroll
        for (int sh = 1; sh < 8; sh <<= 1) {
            int n = __shfl_up_sync(0x000000ffu, inc, sh);
            if (t >= sh) inc += n;
        }
        s_wtot[t] = inc - v;
    }
    __syncthreads();
    int excl = incl - val + s_wtot[w];       // count strictly above seg
    if (excl < KK && excl + val >= KK) {     // unique boundary thread
        int above = excl;
        int cut = seg * 16;
        #pragma unroll
        for (int c = seg * 16 + 15; c >= seg * 16; c--) {
            int hv = hist[c];
            if (above + hv >= KK) { cut = c; break; }
            above += hv;
        }
        *s_cut = ((unsigned)cut) << 20;
    }
}

// ---------------------------------------------------------------------------
// Fused kernel. Grid (1, 45, 16), block 256 (8 warps x 120 output cols).
// launch_bounds(NT, 3): cap regs ~85 so the streaming phase keeps 3 blocks/SM.
// ---------------------------------------------------------------------------
__global__ void __launch_bounds__(NT, 3) fused_kernel(const float* __restrict__ in,
                                                      float* __restrict__ out) {
    __shared__ __align__(16) int shist[HB];  // 16 KB
    __shared__ __align__(16) float2 s_q[QC]; // 16 KB; tail overlays s_d/s_i
    __shared__ int    s_wtot[8];
    __shared__ unsigned s_bcut;
    __shared__ int    s_qcnt, s_keep, s_gbase, s_sel;

    const int b    = blockIdx.z;
    const int by   = blockIdx.y;
    const int tid  = threadIdx.x;
    const int w    = tid >> 5;
    const int lane = tid & 31;

    const int  c0     = w * 120 - 4 + 4 * lane;          // lane's first column
    const bool colok  = ((unsigned)c0 < (unsigned)WW);
    const int  cc     = colok ? c0 : 0;                  // clamped load column
    const bool laneok = (lane >= 1) && (lane <= 30);
    const int  r0     = by * RPB;

    #pragma unroll
    for (int i = tid; i < HB; i += NT) shist[i] = 0;
    if (tid == 0) { s_qcnt = 0; s_keep = 0; s_bcut = 0u; }
    __syncthreads();

    const float* __restrict__ p0 = in + (size_t)b * 2 * HWSZ;
    const float* __restrict__ p1 = p0 + HWSZ;
    int*    __restrict__ gctr = &g_cnt[b];
    float2* __restrict__ gcd  = g_cand[b];

    #define LDROW(R, A, Bv) {                                                  \
        int _rr = (R) < 0 ? 0 : ((R) >= HH ? HH - 1 : (R));                    \
        size_t _o = (size_t)_rr * WW + cc;                                     \
        A  = __ldg(reinterpret_cast<const float4*>(p0 + _o));                  \
        Bv = __ldg(reinterpret_cast<const float4*>(p1 + _o)); }

    #define CVT(A, Bv, R, D) {                                                 \
        if (colok && ((unsigned)(R) < (unsigned)HH))                            \
            D = make_float4(Bv.x - A.x, Bv.y - A.y, Bv.z - A.z, Bv.w - A.w);    \
        else                                                                    \
            D = make_float4(-INFINITY, -INFINITY, -INFINITY, -INFINITY); }

    #define H3MAX4(D, HM) {                                                    \
        float _dl = __shfl_up_sync(0xffffffffu, (D).w, 1);                      \
        float _dr = __shfl_down_sync(0xffffffffu, (D).x, 1);                    \
        (HM).x = fmaxf(_dl,   fmaxf((D).x, (D).y));                             \
        (HM).y = fmaxf((D).x, fmaxf((D).y, (D).z));                             \
        (HM).z = fmaxf((D).y, fmaxf((D).z, (D).w));                             \
        (HM).w = fmaxf((D).z, fmaxf((D).w, _dr)); }

    #define EMIT1(K, V, IDX)                                                   \
        if (K) {                                                               \
            atomicAdd(&shist[fflip(V) >> 20], 1);                              \
            int _p = atomicAdd(&s_qcnt, 1);                                    \
            float2 _v = make_float2(V, __int_as_float(IDX));                   \
            if (_p < QC) s_q[_p] = _v;                                         \
            else { int _g = atomicAdd(gctr, 1);                                \
                   if (_g < CAPG) gcd[_g] = _v; }                              \
        }

    #define EMITROW(DC, HA, HBv, HC, R) {                                      \
        float _m0 = fmaxf((HA).x, fmaxf((HBv).x, (HC).x));                     \
        float _m1 = fmaxf((HA).y, fmaxf((HBv).y, (HC).y));                     \
        float _m2 = fmaxf((HA).z, fmaxf((HBv).z, (HC).z));                     \
        float _m3 = fmaxf((HA).w, fmaxf((HBv).w, (HC).w));                     \
        bool _k0 = laneok && ((DC).x >= _m0);                                  \
        bool _k1 = laneok && ((DC).y >= _m1);                                  \
        bool _k2 = laneok && ((DC).z >= _m2);                                  \
        bool _k3 = laneok && ((DC).w >= _m3);                                  \
        if (_k0 | _k1 | _k2 | _k3) {                                           \
            int _ib = (R) * WW + c0;                                           \
            EMIT1(_k0, (DC).x, _ib)                                            \
            EMIT1(_k1, (DC).y, _ib + 1)                                        \
            EMIT1(_k2, (DC).z, _ib + 2)                                        \
            EMIT1(_k3, (DC).w, _ib + 3)                                        \
        } }

    #define LOAD_GROUP(P, BASE)                                                \
        LDROW((BASE) + 1, P##1a, P##1b)                                        \
        LDROW((BASE) + 2, P##2a, P##2b)                                        \
        LDROW((BASE) + 3, P##3a, P##3b)                                        \
        LDROW((BASE) + 4, P##4a, P##4b)

    #define COMPUTE_GROUP(P, BASE) {                                           \
        float4 _d1, _d2, _d3, _d4, _h1, _h2, _h3, _h4;                         \
        CVT(P##1a, P##1b, (BASE) + 1, _d1)  H3MAX4(_d1, _h1)                   \
        CVT(P##2a, P##2b, (BASE) + 2, _d2)  H3MAX4(_d2, _h2)                   \
        CVT(P##3a, P##3b, (BASE) + 3, _d3)  H3MAX4(_d3, _h3)                   \
        CVT(P##4a, P##4b, (BASE) + 4, _d4)  H3MAX4(_d4, _h4)                   \
        EMITROW(dB, hmA, hmB, _h1, (BASE))                                     \
        EMITROW(_d1, hmB, _h1, _h2, (BASE) + 1)                                \
        EMITROW(_d2, _h1, _h2, _h3, (BASE) + 2)                                \
        EMITROW(_d3, _h2, _h3, _h4, (BASE) + 3)                                \
        hmA = _h3; hmB = _h4; dB = _d4; }

    {
        float4 A1a, A1b, A2a, A2b, A3a, A3b, A4a, A4b;
        float4 B1a, B1b, B2a, B2b, B3a, B3b, B4a, B4b;
        float4 hmA, hmB, dB;
        {
            float4 xa, xb, dm;
            LDROW(r0 - 1, xa, xb)
            LOAD_GROUP(A, r0)                    // rows r0+1..r0+4 (early)
            float4 ya, yb;
            LDROW(r0, ya, yb)
            LOAD_GROUP(B, r0 + 4)                // rows r0+5..r0+8 (early)
            CVT(xa, xb, r0 - 1, dm)  H3MAX4(dm, hmA)
            CVT(ya, yb, r0, dB)      H3MAX4(dB, hmB)
        }
        COMPUTE_GROUP(A, r0)                     // rows r0..r0+3
        LOAD_GROUP(A, r0 + 8)                    // rows r0+9..r0+12 (early)
        COMPUTE_GROUP(B, r0 + 4)                 // rows r0+4..r0+7
        COMPUTE_GROUP(A, r0 + 8)                 // rows r0+8..r0+11
    }

    // --- Block-local top-100 cut + filtered contiguous flush ---------------
    __syncthreads();
    cut_scan256(shist, s_wtot, &s_bcut, tid);
    __syncthreads();
    const unsigned bcut = s_bcut;
    const int qn = min(s_qcnt, QC);

    int cnt = 0;
    for (int i = tid; i < qn; i += NT)
        cnt += (fflip(s_q[i].x) >= bcut);
    if (cnt) atomicAdd(&s_keep, cnt);
    __syncthreads();
    if (tid == 0) {
        s_gbase = (s_keep > 0) ? atomicAdd(gctr, s_keep) : 0;
        s_keep = 0;
    }
    __syncthreads();
    for (int i = tid; i < qn; i += NT) {
        float2 v = s_q[i];
        if (fflip(v.x) >= bcut) {
            int p = s_gbase + atomicAdd(&s_keep, 1);
            if (p < CAPG) gcd[p] = v;
        }
    }

    // =====================================================================
    // Tail: last-arriving block of this batch becomes the selector.
    // Register-cheap: strided loops only, no per-thread arrays.
    // =====================================================================
    __threadfence();                 // release candidate writes
    __syncthreads();
    if (tid == 0)
        s_sel = (atomicAdd(&g_done[b], 1) == NBY - 1) ? 1 : 0;
    __syncthreads();
    if (!s_sel) return;
    __threadfence();                 // acquire side

    const int n = min(*((volatile int*)gctr), CAPG);
    __syncthreads();                 // everyone read n before the reset
    if (tid == 0) { g_cnt[b] = 0; g_done[b] = 0; }   // reset for next replay

    // Re-init smem for the tail; survivor arrays overlay the dead queue.
    #pragma unroll
    for (int i = tid; i < HB; i += NT) shist[i] = 0;
    if (tid == 0) { s_bcut = 0u; s_keep = 0; }
    float* s_d = (float*)s_q;              // 2048 floats (8 KB)
    int*   s_i = ((int*)s_q) + CAP;        // next 2048 ints (8 KB)
    __syncthreads();

    // Pass 1: histogram (strided, unrolled for MLP; data L2-hot).
    #pragma unroll 4
    for (int i = tid; i < n; i += NT)
        atomicAdd(&shist[fflip(gcd[i].x) >> 20], 1);
    __syncthreads();

    cut_scan256(shist, s_wtot, &s_bcut, tid);
    __syncthreads();
    const unsigned cutbits = s_bcut;

    // Pass 2: collect survivors (>= cut); data now L1/L2-hot.
    #pragma unroll 4
    for (int i = tid; i < n; i += NT) {
        float2 vv = gcd[i];
        if (fflip(vv.x) >= cutbits) {
            int pos = atomicAdd(&s_keep, 1);
            if (pos < CAP) { s_d[pos] = vv.x; s_i[pos] = __float_as_int(vv.y); }
        }
    }
    __syncthreads();

    const int C = min(s_keep, CAP);

    // Exact p in place, then exact stable rank: p desc, idx asc.
    for (int e = tid; e < C; e += NT) s_d[e] = prob_from_d(s_d[e]);
    __syncthreads();

    for (int e = tid; e < C; e += NT) {
        const float p  = s_d[e];
        const int   id = s_i[e];
        int rank = 0;
        for (int j = 0; j < C; j++) {
            float pj = s_d[j];
            rank += (pj > p) || (pj == p && s_i[j] < id);
        }
        if (rank < KK) {
            int ww = id % WW;
            int hh = id / WW;
            float xc = (float)ww * 4.0f + 1.5f;
            float yc = (float)hh * 4.0f + 1.5f;
            float* o = out + ((size_t)b * KK + rank) * 5;
            o[0] = xc - 10.0f;
            o[1] = yc - 10.0f;
            o[2] = xc + 10.0f;
            o[3] = yc + 10.0f;
            o[4] = p;
        }
    }
}

// ---------------------------------------------------------------------------
extern "C" void kernel_launch(void* const* d_in, const int* in_sizes, int n_in,
                              void* d_out, int out_size) {
    const float* in = (const float*)d_in[0];
    float* out = (float*)d_out;

    dim3 grid(1, NBY, BB);                    // (1, 45, 16) = 720 blocks
    fused_kernel<<<grid, NT>>>(in, out);
}

// round 14
// speedup vs baseline: 1.5921x; 1.5921x over previous
#include <cuda_runtime.h>
#include <math.h>
#include <stdint.h>

// FootAndBall ball-detection post-process — two kernels (R11 structure).
//  in : [16, 2, 540, 960] fp32 logits
//  out: [16, 100, 5] fp32 (x1,y1,x2,y2,score), score desc (idx asc on ties).
//
//  K1 detect : d = x1-x0 (NMS on d == NMS on softmax prob, monotone).
//    Software-pipelined float4 streaming NMS. Candidates -> block smem queue
//    + smem histogram; TWO-LEVEL block-local top-100 cut (coarse 12-bit bins
//    then 12 more bits inside the cut bin -> 24-bit threshold). R11's 3
//    mantissa-bit bins made the cut bin hold 200-400 entries, quadrupling
//    the flushed volume; refined threshold keeps ~110/block. Queue overflow
//    falls back to direct unfiltered append (superset -> still correct).
//  K2 select : register-burst select over ~5k candidates with the SAME
//    two-level cut -> collected set C ~110 (was ~1000+, whose O(C^2) rank
//    dominated the 27.5us). Exact (p desc, idx asc) rank, box write, reset.
//  __device__ globals start zero-initialized; K2 restores zeros.

#define BB   16
#define HH   540
#define WW   960
#define HWSZ (HH * WW)
#define KK   100

#define NT    256                 // detect threads per block (8 warps)
#define RPB   12                  // rows per block; 540 = 45 * 12
#define NBY   45                  // blocks per batch
#define QC    2048                // block smem queue entries (16 KB)
#define HB    4096                // histogram bins (12 bits per level)
#define CAP   2048                // select survivor capacity (expected ~150)
#define CAPG  65536               // per-batch global candidate capacity
#define RPT   16                  // select: candidates per thread (512*16=8192)

__device__ int    g_cnt [BB];
__device__ float2 g_cand[BB][CAPG];

// ---------------------------------------------------------------------------
// Exact softmax channel-1 prob from d = fl(x1-x0). Matches jax.nn.softmax:
// one exp arg is exactly 0 and fl(x0-x1) == -d exactly. (rel_err ~1e-12.)
// ---------------------------------------------------------------------------
__device__ __forceinline__ float prob_from_d(float d) {
#ifdef __FAST_MATH__
    double dd = (double)d;
    double p = (d >= 0.0f) ? (1.0 / (exp(-dd) + 1.0))
                           : (exp(dd) / (exp(dd) + 1.0));
    return (float)p;
#else
    if (d >= 0.0f) { float e0 = expf(-d); return 1.0f / (e0 + 1.0f); }
    else           { float e1 = expf(d);  return e1 / (1.0f + e1);  }
#endif
}

// Order-preserving bit flip: float compare == unsigned compare after flip.
__device__ __forceinline__ unsigned fflip(float f) {
    unsigned u = __float_as_uint(f);
    return u ^ (((unsigned)((int)u >> 31)) | 0x80000000u);
}

// ---------------------------------------------------------------------------
// Log-parallel cut over a 4096-bin smem histogram.
// Finds smallest bin c with count(bin >= c) >= K; writes *s_cutbin = c and
// *s_above = count(bin > c). If total < K, leaves both untouched (caller
// pre-zeroes -> cut 0 / above 0 -> keep-everything fallback).
// Caller zeroes outputs + syncs before; must sync after.
// ---------------------------------------------------------------------------
__device__ __forceinline__ void cut_scan256x(const int* __restrict__ hist,
                                             int* __restrict__ s_wtot,
                                             int* __restrict__ s_cutbin,
                                             int* __restrict__ s_above,
                                             int K, int t) {
    const int lane = t & 31;
    const int w    = t >> 5;
    const int seg  = 255 - t;                // descending bin order
    int val = 0;
    const int4* h4 = (const int4*)(hist + seg * 16);
    #pragma unroll
    for (int j = 0; j < 4; j++) { int4 a = h4[j]; val += a.x + a.y + a.z + a.w; }

    int incl = val;
    #pragma unroll
    for (int sh = 1; sh < 32; sh <<= 1) {
        int n = __shfl_up_sync(0xffffffffu, incl, sh);
        if (lane >= sh) incl += n;
    }
    if (lane == 31) s_wtot[w] = incl;
    __syncthreads();
    if (t < 8) {
        int v = s_wtot[t];
        int inc = v;
        #pragma unroll
        for (int sh = 1; sh < 8; sh <<= 1) {
            int n = __shfl_up_sync(0x000000ffu, inc, sh);
            if (t >= sh) inc += n;
        }
        s_wtot[t] = inc - v;
    }
    __syncthreads();
    int excl = incl - val + s_wtot[w];       // count strictly above seg
    if (excl < K && excl + val >= K) {       // unique boundary thread
        int above = excl;
        int cut = seg * 16;
        #pragma unroll
        for (int c = seg * 16 + 15; c >= seg * 16; c--) {
            int hv = hist[c];
            if (above + hv >= K) { cut = c; break; }
            above += hv;
        }
        *s_cutbin = cut;
        *s_above  = above;
    }
}

// 512-thread variant (8 bins per thread) for the select kernel.
__device__ __forceinline__ void cut_scan512x(const int* __restrict__ hist,
                                             int* __restrict__ s_wtot,
                                             int* __restrict__ s_cutbin,
                                             int* __restrict__ s_above,
                                             int K, int t) {
    const int lane = t & 31;
    const int w    = t >> 5;
    const int seg  = 511 - t;
    int val = 0;
    const int4* h4 = (const int4*)(hist + seg * 8);
    #pragma unroll
    for (int j = 0; j < 2; j++) { int4 a = h4[j]; val += a.x + a.y + a.z + a.w; }

    int incl = val;
    #pragma unroll
    for (int sh = 1; sh < 32; sh <<= 1) {
        int n = __shfl_up_sync(0xffffffffu, incl, sh);
        if (lane >= sh) incl += n;
    }
    if (lane == 31) s_wtot[w] = incl;
    __syncthreads();
    if (t < 16) {
        int v = s_wtot[t];
        int inc = v;
        #pragma unroll
        for (int sh = 1; sh < 16; sh <<= 1) {
            int n = __shfl_up_sync(0x0000ffffu, inc, sh);
            if (t >= sh) inc += n;
        }
        s_wtot[t] = inc - v;
    }
    __syncthreads();
    int excl = incl - val + s_wtot[w];
    if (excl < K && excl + val >= K) {
        int above = excl;
        int cut = seg * 8;
        #pragma unroll
        for (int c = seg * 8 + 7; c >= seg * 8; c--) {
            int hv = hist[c];
            if (above + hv >= K) { cut = c; break; }
            above += hv;
        }
        *s_cutbin = cut;
        *s_above  = above;
    }
}

// ---------------------------------------------------------------------------
// K1: pipelined register-streaming NMS + two-level block filter + flush.
// Grid (1, 45, 16), block 256 (8 warps x 120 output cols, 12 rows).
// ---------------------------------------------------------------------------
__global__ __launch_bounds__(NT) void detect_kernel(const float* __restrict__ in) {
    __shared__ __align__(16) int shist[HB];  // 16 KB
    __shared__ float2 s_q[QC];               // 16 KB
    __shared__ int    s_wtot[8];
    __shared__ int    s_cb, s_ab, s_rb, s_du;
    __shared__ int    s_qcnt, s_keep, s_gbase;

    const int b    = blockIdx.z;
    const int by   = blockIdx.y;
    const int tid  = threadIdx.x;
    const int w    = tid >> 5;
    const int lane = tid & 31;

    const int  c0     = w * 120 - 4 + 4 * lane;          // lane's first column
    const bool colok  = ((unsigned)c0 < (unsigned)WW);
    const int  cc     = colok ? c0 : 0;                  // clamped load column
    const bool laneok = (lane >= 1) && (lane <= 30);
    const int  r0     = by * RPB;

    #pragma unroll
    for (int i = tid; i < HB; i += NT) shist[i] = 0;
    if (tid == 0) { s_qcnt = 0; s_keep = 0; s_cb = 0; s_ab = 0; s_rb = 0; s_du = 0; }
    __syncthreads();

    const float* __restrict__ p0 = in + (size_t)b * 2 * HWSZ;
    const float* __restrict__ p1 = p0 + HWSZ;
    int*    __restrict__ gctr = &g_cnt[b];
    float2* __restrict__ gcd  = g_cand[b];

    #define LDROW(R, A, Bv) {                                                  \
        int _rr = (R) < 0 ? 0 : ((R) >= HH ? HH - 1 : (R));                    \
        size_t _o = (size_t)_rr * WW + cc;                                     \
        A  = __ldg(reinterpret_cast<const float4*>(p0 + _o));                  \
        Bv = __ldg(reinterpret_cast<const float4*>(p1 + _o)); }

    #define CVT(A, Bv, R, D) {                                                 \
        if (colok && ((unsigned)(R) < (unsigned)HH))                            \
            D = make_float4(Bv.x - A.x, Bv.y - A.y, Bv.z - A.z, Bv.w - A.w);    \
        else                                                                    \
            D = make_float4(-INFINITY, -INFINITY, -INFINITY, -INFINITY); }

    #define H3MAX4(D, HM) {                                                    \
        float _dl = __shfl_up_sync(0xffffffffu, (D).w, 1);                      \
        float _dr = __shfl_down_sync(0xffffffffu, (D).x, 1);                    \
        (HM).x = fmaxf(_dl,   fmaxf((D).x, (D).y));                             \
        (HM).y = fmaxf((D).x, fmaxf((D).y, (D).z));                             \
        (HM).z = fmaxf((D).y, fmaxf((D).z, (D).w));                             \
        (HM).w = fmaxf((D).z, fmaxf((D).w, _dr)); }

    #define EMIT1(K, V, IDX)                                                   \
        if (K) {                                                               \
            atomicAdd(&shist[fflip(V) >> 20], 1);                              \
            int _p = atomicAdd(&s_qcnt, 1);                                    \
            float2 _v = make_float2(V, __int_as_float(IDX));                   \
            if (_p < QC) s_q[_p] = _v;                                         \
            else { int _g = atomicAdd(gctr, 1);                                \
                   if (_g < CAPG) gcd[_g] = _v; }                              \
        }

    #define EMITROW(DC, HA, HBv, HC, R) {                                      \
        float _m0 = fmaxf((HA).x, fmaxf((HBv).x, (HC).x));                     \
        float _m1 = fmaxf((HA).y, fmaxf((HBv).y, (HC).y));                     \
        float _m2 = fmaxf((HA).z, fmaxf((HBv).z, (HC).z));                     \
        float _m3 = fmaxf((HA).w, fmaxf((HBv).w, (HC).w));                     \
        bool _k0 = laneok && ((DC).x >= _m0);                                  \
        bool _k1 = laneok && ((DC).y >= _m1);                                  \
        bool _k2 = laneok && ((DC).z >= _m2);                                  \
        bool _k3 = laneok && ((DC).w >= _m3);                                  \
        if (_k0 | _k1 | _k2 | _k3) {                                           \
            int _ib = (R) * WW + c0;                                           \
            EMIT1(_k0, (DC).x, _ib)                                            \
            EMIT1(_k1, (DC).y, _ib + 1)                                        \
            EMIT1(_k2, (DC).z, _ib + 2)                                        \
            EMIT1(_k3, (DC).w, _ib + 3)                                        \
        } }

    #define LOAD_GROUP(P, BASE)                                                \
        LDROW((BASE) + 1, P##1a, P##1b)                                        \
        LDROW((BASE) + 2, P##2a, P##2b)                                        \
        LDROW((BASE) + 3, P##3a, P##3b)                                        \
        LDROW((BASE) + 4, P##4a, P##4b)

    #define COMPUTE_GROUP(P, BASE) {                                           \
        float4 _d1, _d2, _d3, _d4, _h1, _h2, _h3, _h4;                         \
        CVT(P##1a, P##1b, (BASE) + 1, _d1)  H3MAX4(_d1, _h1)                   \
        CVT(P##2a, P##2b, (BASE) + 2, _d2)  H3MAX4(_d2, _h2)                   \
        CVT(P##3a, P##3b, (BASE) + 3, _d3)  H3MAX4(_d3, _h3)                   \
        CVT(P##4a, P##4b, (BASE) + 4, _d4)  H3MAX4(_d4, _h4)                   \
        EMITROW(dB, hmA, hmB, _h1, (BASE))                                     \
        EMITROW(_d1, hmB, _h1, _h2, (BASE) + 1)                                \
        EMITROW(_d2, _h1, _h2, _h3, (BASE) + 2)                                \
        EMITROW(_d3, _h2, _h3, _h4, (BASE) + 3)                                \
        hmA = _h3; hmB = _h4; dB = _d4; }

    {
        float4 A1a, A1b, A2a, A2b, A3a, A3b, A4a, A4b;
        float4 B1a, B1b, B2a, B2b, B3a, B3b, B4a, B4b;
        float4 hmA, hmB, dB;
        {
            float4 xa, xb, dm;
            LDROW(r0 - 1, xa, xb)
            LOAD_GROUP(A, r0)                    // rows r0+1..r0+4 (early)
            float4 ya, yb;
            LDROW(r0, ya, yb)
            LOAD_GROUP(B, r0 + 4)                // rows r0+5..r0+8 (early)
            CVT(xa, xb, r0 - 1, dm)  H3MAX4(dm, hmA)
            CVT(ya, yb, r0, dB)      H3MAX4(dB, hmB)
        }
        COMPUTE_GROUP(A, r0)                     // rows r0..r0+3
        LOAD_GROUP(A, r0 + 8)                    // rows r0+9..r0+12 (early)
        COMPUTE_GROUP(B, r0 + 4)                 // rows r0+4..r0+7
        COMPUTE_GROUP(A, r0 + 8)                 // rows r0+8..r0+11
    }

    // --- Two-level block-local top-100 cut ----------------------------------
    __syncthreads();
    cut_scan256x(shist, s_wtot, &s_cb, &s_ab, KK, tid);
    __syncthreads();
    const int cb = s_cb, ab = s_ab;
    const int qn = min(s_qcnt, QC);

    #pragma unroll
    for (int i = tid; i < HB; i += NT) shist[i] = 0;   // re-zero for refine
    __syncthreads();
    for (int i = tid; i < qn; i += NT) {
        unsigned f = fflip(s_q[i].x);
        if ((int)(f >> 20) == cb) atomicAdd(&shist[(f >> 8) & 0xFFFu], 1);
    }
    __syncthreads();
    cut_scan256x(shist, s_wtot, &s_rb, &s_du, KK - ab, tid);
    __syncthreads();
    const unsigned bthr = ((unsigned)cb << 20) | ((unsigned)s_rb << 8);

    // --- Filtered contiguous flush of the queue -----------------------------
    int cnt = 0;
    for (int i = tid; i < qn; i += NT)
        cnt += (fflip(s_q[i].x) >= bthr);
    if (cnt) atomicAdd(&s_keep, cnt);
    __syncthreads();
    if (tid == 0) {
        s_gbase = (s_keep > 0) ? atomicAdd(gctr, s_keep) : 0;
        s_keep = 0;
    }
    __syncthreads();
    for (int i = tid; i < qn; i += NT) {
        float2 v = s_q[i];
        if (fflip(v.x) >= bthr) {
            int p = s_gbase + atomicAdd(&s_keep, 1);
            if (p < CAPG) gcd[p] = v;
        }
    }
}

// ---------------------------------------------------------------------------
// K2: register-burst per-batch top-100 with two-level cut. Grid BB, block 512.
// ---------------------------------------------------------------------------
__global__ __launch_bounds__(512) void select_kernel(float* __restrict__ out) {
    __shared__ __align__(16) int shist[HB];  // 16 KB
    __shared__ int      s_wtot[16];
    __shared__ int      s_cb, s_ab, s_rb, s_du;
    __shared__ int      s_count;
    __shared__ float    s_d[CAP];            // 8 KB (d, overwritten by p)
    __shared__ int      s_i[CAP];            // 8 KB

    const int b = blockIdx.x;
    const int t = threadIdx.x;

    {   // vectorized smem hist zero
        int4* h4 = (int4*)shist;
        h4[t]       = make_int4(0, 0, 0, 0);
        h4[t + 512] = make_int4(0, 0, 0, 0);
    }
    if (t == 0) { s_cb = 0; s_ab = 0; s_rb = 0; s_du = 0; s_count = 0; }

    const int n = min(g_cnt[b], CAPG);
    if (t == 0) g_cnt[b] = 0;               // reset for next graph replay
    const float2* __restrict__ cd = g_cand[b];

    // ---- One unpredicated load burst ----
    float2 v[RPT];
    #pragma unroll
    for (int j = 0; j < RPT; j++) {
        int idx = t + j * 512;
        int ii  = (idx < n) ? idx : 0;       // clamp keeps the load legal
        v[j] = __ldg(cd + ii);
    }
    __syncthreads();                          // hist zero complete

    // ---- Coarse histogram from registers ----
    #pragma unroll
    for (int j = 0; j < RPT; j++)
        if (t + j * 512 < n)
            atomicAdd(&shist[fflip(v[j].x) >> 20], 1);
    for (int i = 512 * RPT + t; i < n; i += 512)      // rare overflow
        atomicAdd(&shist[fflip(cd[i].x) >> 20], 1);
    __syncthreads();

    cut_scan512x(shist, s_wtot, &s_cb, &s_ab, KK, t);
    __syncthreads();
    const int cb = s_cb, ab = s_ab;

    // ---- Refine: histogram of bits [8:20) inside the cut bin ----
    {
        int4* h4 = (int4*)shist;
        h4[t]       = make_int4(0, 0, 0, 0);
        h4[t + 512] = make_int4(0, 0, 0, 0);
    }
    __syncthreads();
    #pragma unroll
    for (int j = 0; j < RPT; j++) {
        if (t + j * 512 < n) {
            unsigned f = fflip(v[j].x);
            if ((int)(f >> 20) == cb) atomicAdd(&shist[(f >> 8) & 0xFFFu], 1);
        }
    }
    for (int i = 512 * RPT + t; i < n; i += 512) {    // rare overflow
        unsigned f = fflip(cd[i].x);
        if ((int)(f >> 20) == cb) atomicAdd(&shist[(f >> 8) & 0xFFFu], 1);
    }
    __syncthreads();
    cut_scan512x(shist, s_wtot, &s_rb, &s_du, KK - ab, t);
    __syncthreads();
    const unsigned thr = ((unsigned)cb << 20) | ((unsigned)s_rb << 8);

    // ---- Collect survivors from registers (C ~ 110-200) ----
    #pragma unroll
    for (int j = 0; j < RPT; j++) {
        if (t + j * 512 < n && fflip(v[j].x) >= thr) {
            int pos = atomicAdd(&s_count, 1);
            if (pos < CAP) { s_d[pos] = v[j].x; s_i[pos] = __float_as_int(v[j].y); }
        }
    }
    for (int i = 512 * RPT + t; i < n; i += 512) {    // rare overflow
        float2 vv = cd[i];
        if (fflip(vv.x) >= thr) {
            int pos = atomicAdd(&s_count, 1);
            if (pos < CAP) { s_d[pos] = vv.x; s_i[pos] = __float_as_int(vv.y); }
        }
    }
    __syncthreads();

    const int C = min(s_count, CAP);

    // ---- Exact p in place, then exact stable rank: p desc, idx asc ----
    for (int e = t; e < C; e += 512) s_d[e] = prob_from_d(s_d[e]);
    __syncthreads();

    for (int e = t; e < C; e += 512) {
        const float p  = s_d[e];
        const int   id = s_i[e];
        int rank = 0;
        for (int j = 0; j < C; j++) {
            float pj = s_d[j];
            rank += (pj > p) || (pj == p && s_i[j] < id);
        }
        if (rank < KK) {
            int ww = id % WW;
            int hh = id / WW;
            float xc = (float)ww * 4.0f + 1.5f;
            float yc = (float)hh * 4.0f + 1.5f;
            float* o = out + ((size_t)b * KK + rank) * 5;
            o[0] = xc - 10.0f;
            o[1] = yc - 10.0f;
            o[2] = xc + 10.0f;
            o[3] = yc + 10.0f;
            o[4] = p;
        }
    }
}

// ---------------------------------------------------------------------------
extern "C" void kernel_launch(void* const* d_in, const int* in_sizes, int n_in,
                              void* d_out, int out_size) {
    const float* in = (const float*)d_in[0];
    float* out = (float*)d_out;

    dim3 grid(1, NBY, BB);                    // (1, 45, 16) = 720 blocks
    detect_kernel<<<grid, NT>>>(in);

    select_kernel<<<BB, 512>>>(out);
}

// round 15
// speedup vs baseline: 1.5931x; 1.0007x over previous
#include <cuda_runtime.h>
#include <math.h>
#include <stdint.h>

// FootAndBall ball-detection post-process — two kernels.
//  in : [16, 2, 540, 960] fp32 logits
//  out: [16, 100, 5] fp32 (x1,y1,x2,y2,score), score desc (idx asc on ties).
//
//  K1 detect : d = x1-x0 (NMS on d == NMS on softmax prob, monotone).
//    Software-pipelined float4 streaming NMS. Emission is WARP-AGGREGATED:
//    4 ballots + popc offsets + ONE s_qcnt atomic per (warp,row) — R14 did
//    ~2540 contended smem atomics per block (2 per candidate; ~11% of pixels
//    survive 3x3 NMS), which serialized the ATOMS pipe. The block histogram
//    is built AFTER the loop from the queue itself (queue is re-scanned for
//    the cut anyway). TWO-LEVEL block-local top-100 cut (24-bit threshold)
//    filters to ~110/block before ONE contiguous per-batch flush.
//    Cut is over queue members only: any block-top-100 element is either in
//    the queue (rank in queue <= rank in block <= 100 -> kept) or overflowed
//    (flushed unfiltered) -> flushed set still superset of block top-100.
//  K2 select : register-burst select with the same two-level cut (C ~ 150),
//    exact (p desc, idx asc) rank, box write, counter reset. (R14, unchanged)
//  __device__ globals start zero-initialized; K2 restores zeros.

#define BB   16
#define HH   540
#define WW   960
#define HWSZ (HH * WW)
#define KK   100

#define NT    256                 // detect threads per block (8 warps)
#define RPB   12                  // rows per block; 540 = 45 * 12
#define NBY   45                  // blocks per batch
#define QC    2048                // block smem queue entries (16 KB)
#define HB    4096                // histogram bins (12 bits per level)
#define CAP   2048                // select survivor capacity (expected ~150)
#define CAPG  65536               // per-batch global candidate capacity
#define RPT   16                  // select: candidates per thread (512*16=8192)

__device__ int    g_cnt [BB];
__device__ float2 g_cand[BB][CAPG];

// ---------------------------------------------------------------------------
// Exact softmax channel-1 prob from d = fl(x1-x0). Matches jax.nn.softmax:
// one exp arg is exactly 0 and fl(x0-x1) == -d exactly. (rel_err ~1e-12.)
// ---------------------------------------------------------------------------
__device__ __forceinline__ float prob_from_d(float d) {
#ifdef __FAST_MATH__
    double dd = (double)d;
    double p = (d >= 0.0f) ? (1.0 / (exp(-dd) + 1.0))
                           : (exp(dd) / (exp(dd) + 1.0));
    return (float)p;
#else
    if (d >= 0.0f) { float e0 = expf(-d); return 1.0f / (e0 + 1.0f); }
    else           { float e1 = expf(d);  return e1 / (1.0f + e1);  }
#endif
}

// Order-preserving bit flip: float compare == unsigned compare after flip.
__device__ __forceinline__ unsigned fflip(float f) {
    unsigned u = __float_as_uint(f);
    return u ^ (((unsigned)((int)u >> 31)) | 0x80000000u);
}

// ---------------------------------------------------------------------------
// Log-parallel cut over a 4096-bin smem histogram.
// Finds smallest bin c with count(bin >= c) >= K; writes *s_cutbin = c and
// *s_above = count(bin > c). If total < K, leaves both untouched (caller
// pre-zeroes -> keep-everything fallback).
// ---------------------------------------------------------------------------
__device__ __forceinline__ void cut_scan256x(const int* __restrict__ hist,
                                             int* __restrict__ s_wtot,
                                             int* __restrict__ s_cutbin,
                                             int* __restrict__ s_above,
                                             int K, int t) {
    const int lane = t & 31;
    const int w    = t >> 5;
    const int seg  = 255 - t;                // descending bin order
    int val = 0;
    const int4* h4 = (const int4*)(hist + seg * 16);
    #pragma unroll
    for (int j = 0; j < 4; j++) { int4 a = h4[j]; val += a.x + a.y + a.z + a.w; }

    int incl = val;
    #pragma unroll
    for (int sh = 1; sh < 32; sh <<= 1) {
        int n = __shfl_up_sync(0xffffffffu, incl, sh);
        if (lane >= sh) incl += n;
    }
    if (lane == 31) s_wtot[w] = incl;
    __syncthreads();
    if (t < 8) {
        int v = s_wtot[t];
        int inc = v;
        #pragma unroll
        for (int sh = 1; sh < 8; sh <<= 1) {
            int n = __shfl_up_sync(0x000000ffu, inc, sh);
            if (t >= sh) inc += n;
        }
        s_wtot[t] = inc - v;
    }
    __syncthreads();
    int excl = incl - val + s_wtot[w];       // count strictly above seg
    if (excl < K && excl + val >= K) {       // unique boundary thread
        int above = excl;
        int cut = seg * 16;
        #pragma unroll
        for (int c = seg * 16 + 15; c >= seg * 16; c--) {
            int hv = hist[c];
            if (above + hv >= K) { cut = c; break; }
            above += hv;
        }
        *s_cutbin = cut;
        *s_above  = above;
    }
}

// 512-thread variant (8 bins per thread) for the select kernel.
__device__ __forceinline__ void cut_scan512x(const int* __restrict__ hist,
                                             int* __restrict__ s_wtot,
                                             int* __restrict__ s_cutbin,
                                             int* __restrict__ s_above,
                                             int K, int t) {
    const int lane = t & 31;
    const int w    = t >> 5;
    const int seg  = 511 - t;
    int val = 0;
    const int4* h4 = (const int4*)(hist + seg * 8);
    #pragma unroll
    for (int j = 0; j < 2; j++) { int4 a = h4[j]; val += a.x + a.y + a.z + a.w; }

    int incl = val;
    #pragma unroll
    for (int sh = 1; sh < 32; sh <<= 1) {
        int n = __shfl_up_sync(0xffffffffu, incl, sh);
        if (lane >= sh) incl += n;
    }
    if (lane == 31) s_wtot[w] = incl;
    __syncthreads();
    if (t < 16) {
        int v = s_wtot[t];
        int inc = v;
        #pragma unroll
        for (int sh = 1; sh < 16; sh <<= 1) {
            int n = __shfl_up_sync(0x0000ffffu, inc, sh);
            if (t >= sh) inc += n;
        }
        s_wtot[t] = inc - v;
    }
    __syncthreads();
    int excl = incl - val + s_wtot[w];
    if (excl < K && excl + val >= K) {
        int above = excl;
        int cut = seg * 8;
        #pragma unroll
        for (int c = seg * 8 + 7; c >= seg * 8; c--) {
            int hv = hist[c];
            if (above + hv >= K) { cut = c; break; }
            above += hv;
        }
        *s_cutbin = cut;
        *s_above  = above;
    }
}

// ---------------------------------------------------------------------------
// K1: pipelined register-streaming NMS + warp-aggregated emit + 2-level cut.
// Grid (1, 45, 16), block 256 (8 warps x 120 output cols, 12 rows).
// ---------------------------------------------------------------------------
__global__ __launch_bounds__(NT) void detect_kernel(const float* __restrict__ in) {
    __shared__ __align__(16) int shist[HB];  // 16 KB
    __shared__ float2 s_q[QC];               // 16 KB
    __shared__ int    s_wtot[8];
    __shared__ int    s_cb, s_ab, s_rb, s_du;
    __shared__ int    s_qcnt, s_keep, s_gbase;

    const int b    = blockIdx.z;
    const int by   = blockIdx.y;
    const int tid  = threadIdx.x;
    const int w    = tid >> 5;
    const int lane = tid & 31;

    const int  c0     = w * 120 - 4 + 4 * lane;          // lane's first column
    const bool colok  = ((unsigned)c0 < (unsigned)WW);
    const int  cc     = colok ? c0 : 0;                  // clamped load column
    const bool laneok = (lane >= 1) && (lane <= 30);
    const unsigned lmask = (1u << lane) - 1u;
    const int  r0     = by * RPB;

    if (tid == 0) { s_qcnt = 0; s_keep = 0; s_cb = 0; s_ab = 0; s_rb = 0; s_du = 0; }
    __syncthreads();

    const float* __restrict__ p0 = in + (size_t)b * 2 * HWSZ;
    const float* __restrict__ p1 = p0 + HWSZ;
    int*    __restrict__ gctr = &g_cnt[b];
    float2* __restrict__ gcd  = g_cand[b];

    #define LDROW(R, A, Bv) {                                                  \
        int _rr = (R) < 0 ? 0 : ((R) >= HH ? HH - 1 : (R));                    \
        size_t _o = (size_t)_rr * WW + cc;                                     \
        A  = __ldg(reinterpret_cast<const float4*>(p0 + _o));                  \
        Bv = __ldg(reinterpret_cast<const float4*>(p1 + _o)); }

    #define CVT(A, Bv, R, D) {                                                 \
        if (colok && ((unsigned)(R) < (unsigned)HH))                            \
            D = make_float4(Bv.x - A.x, Bv.y - A.y, Bv.z - A.z, Bv.w - A.w);    \
        else                                                                    \
            D = make_float4(-INFINITY, -INFINITY, -INFINITY, -INFINITY); }

    #define H3MAX4(D, HM) {                                                    \
        float _dl = __shfl_up_sync(0xffffffffu, (D).w, 1);                      \
        float _dr = __shfl_down_sync(0xffffffffu, (D).x, 1);                    \
        (HM).x = fmaxf(_dl,   fmaxf((D).x, (D).y));                             \
        (HM).y = fmaxf((D).x, fmaxf((D).y, (D).z));                             \
        (HM).z = fmaxf((D).y, fmaxf((D).z, (D).w));                             \
        (HM).w = fmaxf((D).z, fmaxf((D).w, _dr)); }

    // Queue put with global overflow fallback (unfiltered -> superset, OK).
    #define QPUT(P, V, I) {                                                    \
        float2 _v = make_float2(V, __int_as_float(I));                          \
        if ((P) < QC) s_q[P] = _v;                                              \
        else { int _g = atomicAdd(gctr, 1); if (_g < CAPG) gcd[_g] = _v; } }

    // Warp-aggregated emission: 4 ballots, ONE s_qcnt atomic per (warp,row).
    #define EMITROW(DC, HA, HBv, HC, R) {                                      \
        float _m0 = fmaxf((HA).x, fmaxf((HBv).x, (HC).x));                     \
        float _m1 = fmaxf((HA).y, fmaxf((HBv).y, (HC).y));                     \
        float _m2 = fmaxf((HA).z, fmaxf((HBv).z, (HC).z));                     \
        float _m3 = fmaxf((HA).w, fmaxf((HBv).w, (HC).w));                     \
        bool _k0 = laneok && ((DC).x >= _m0);                                  \
        bool _k1 = laneok && ((DC).y >= _m1);                                  \
        bool _k2 = laneok && ((DC).z >= _m2);                                  \
        bool _k3 = laneok && ((DC).w >= _m3);                                  \
        unsigned _b0 = __ballot_sync(0xffffffffu, _k0);                        \
        unsigned _b1 = __ballot_sync(0xffffffffu, _k1);                        \
        unsigned _b2 = __ballot_sync(0xffffffffu, _k2);                        \
        unsigned _b3 = __ballot_sync(0xffffffffu, _k3);                        \
        int _n0 = __popc(_b0), _n1 = __popc(_b1);                              \
        int _n2 = __popc(_b2), _n3 = __popc(_b3);                              \
        int _nc = _n0 + _n1 + _n2 + _n3;                                       \
        if (_nc) {                                                             \
            int _base = 0;                                                     \
            if (lane == 0) _base = atomicAdd(&s_qcnt, _nc);                    \
            _base = __shfl_sync(0xffffffffu, _base, 0);                        \
            int _ib = (R) * WW + c0;                                           \
            if (_k0) QPUT(_base + __popc(_b0 & lmask), (DC).x, _ib)            \
            if (_k1) QPUT(_base + _n0 + __popc(_b1 & lmask), (DC).y, _ib + 1)  \
            if (_k2) QPUT(_base + _n0 + _n1 + __popc(_b2 & lmask),             \
                          (DC).z, _ib + 2)                                     \
            if (_k3) QPUT(_base + _n0 + _n1 + _n2 + __popc(_b3 & lmask),       \
                          (DC).w, _ib + 3)                                     \
        } }

    #define LOAD_GROUP(P, BASE)                                                \
        LDROW((BASE) + 1, P##1a, P##1b)                                        \
        LDROW((BASE) + 2, P##2a, P##2b)                                        \
        LDROW((BASE) + 3, P##3a, P##3b)                                        \
        LDROW((BASE) + 4, P##4a, P##4b)

    #define COMPUTE_GROUP(P, BASE) {                                           \
        float4 _d1, _d2, _d3, _d4, _h1, _h2, _h3, _h4;                         \
        CVT(P##1a, P##1b, (BASE) + 1, _d1)  H3MAX4(_d1, _h1)                   \
        CVT(P##2a, P##2b, (BASE) + 2, _d2)  H3MAX4(_d2, _h2)                   \
        CVT(P##3a, P##3b, (BASE) + 3, _d3)  H3MAX4(_d3, _h3)                   \
        CVT(P##4a, P##4b, (BASE) + 4, _d4)  H3MAX4(_d4, _h4)                   \
        EMITROW(dB, hmA, hmB, _h1, (BASE))                                     \
        EMITROW(_d1, hmB, _h1, _h2, (BASE) + 1)                                \
        EMITROW(_d2, _h1, _h2, _h3, (BASE) + 2)                                \
        EMITROW(_d3, _h2, _h3, _h4, (BASE) + 3)                                \
        hmA = _h3; hmB = _h4; dB = _d4; }

    {
        float4 A1a, A1b, A2a, A2b, A3a, A3b, A4a, A4b;
        float4 B1a, B1b, B2a, B2b, B3a, B3b, B4a, B4b;
        float4 hmA, hmB, dB;
        {
            float4 xa, xb, dm;
            LDROW(r0 - 1, xa, xb)
            LOAD_GROUP(A, r0)                    // rows r0+1..r0+4 (early)
            float4 ya, yb;
            LDROW(r0, ya, yb)
            LOAD_GROUP(B, r0 + 4)                // rows r0+5..r0+8 (early)
            CVT(xa, xb, r0 - 1, dm)  H3MAX4(dm, hmA)
            CVT(ya, yb, r0, dB)      H3MAX4(dB, hmB)
        }
        COMPUTE_GROUP(A, r0)                     // rows r0..r0+3
        LOAD_GROUP(A, r0 + 8)                    // rows r0+9..r0+12 (early)
        COMPUTE_GROUP(B, r0 + 4)                 // rows r0+4..r0+7
        COMPUTE_GROUP(A, r0 + 8)                 // rows r0+8..r0+11
    }
    __syncthreads();

    const int qn = min(s_qcnt, QC);

    // --- Deferred histogram over queue members ------------------------------
    #pragma unroll
    for (int i = tid; i < HB; i += NT) shist[i] = 0;
    __syncthreads();
    for (int i = tid; i < qn; i += NT)
        atomicAdd(&shist[fflip(s_q[i].x) >> 20], 1);
    __syncthreads();

    // --- Two-level block-local top-100 cut ----------------------------------
    cut_scan256x(shist, s_wtot, &s_cb, &s_ab, KK, tid);
    __syncthreads();
    const int cb = s_cb, ab = s_ab;

    #pragma unroll
    for (int i = tid; i < HB; i += NT) shist[i] = 0;   // re-zero for refine
    __syncthreads();
    for (int i = tid; i < qn; i += NT) {
        unsigned f = fflip(s_q[i].x);
        if ((int)(f >> 20) == cb) atomicAdd(&shist[(f >> 8) & 0xFFFu], 1);
    }
    __syncthreads();
    cut_scan256x(shist, s_wtot, &s_rb, &s_du, KK - ab, tid);
    __syncthreads();
    const unsigned bthr = ((unsigned)cb << 20) | ((unsigned)s_rb << 8);

    // --- Filtered contiguous flush of the queue -----------------------------
    int cnt = 0;
    for (int i = tid; i < qn; i += NT)
        cnt += (fflip(s_q[i].x) >= bthr);
    if (cnt) atomicAdd(&s_keep, cnt);
    __syncthreads();
    if (tid == 0) {
        s_gbase = (s_keep > 0) ? atomicAdd(gctr, s_keep) : 0;
        s_keep = 0;
    }
    __syncthreads();
    for (int i = tid; i < qn; i += NT) {
        float2 v = s_q[i];
        if (fflip(v.x) >= bthr) {
            int p = s_gbase + atomicAdd(&s_keep, 1);
            if (p < CAPG) gcd[p] = v;
        }
    }
}

// ---------------------------------------------------------------------------
// K2: register-burst per-batch top-100 with two-level cut. Grid BB, block 512.
// (Unchanged from R14.)
// ---------------------------------------------------------------------------
__global__ __launch_bounds__(512) void select_kernel(float* __restrict__ out) {
    __shared__ __align__(16) int shist[HB];  // 16 KB
    __shared__ int      s_wtot[16];
    __shared__ int      s_cb, s_ab, s_rb, s_du;
    __shared__ int      s_count;
    __shared__ float    s_d[CAP];            // 8 KB (d, overwritten by p)
    __shared__ int      s_i[CAP];            // 8 KB

    const int b = blockIdx.x;
    const int t = threadIdx.x;

    {   // vectorized smem hist zero
        int4* h4 = (int4*)shist;
        h4[t]       = make_int4(0, 0, 0, 0);
        h4[t + 512] = make_int4(0, 0, 0, 0);
    }
    if (t == 0) { s_cb = 0; s_ab = 0; s_rb = 0; s_du = 0; s_count = 0; }

    const int n = min(g_cnt[b], CAPG);
    if (t == 0) g_cnt[b] = 0;               // reset for next graph replay
    const float2* __restrict__ cd = g_cand[b];

    // ---- One unpredicated load burst ----
    float2 v[RPT];
    #pragma unroll
    for (int j = 0; j < RPT; j++) {
        int idx = t + j * 512;
        int ii  = (idx < n) ? idx : 0;       // clamp keeps the load legal
        v[j] = __ldg(cd + ii);
    }
    __syncthreads();                          // hist zero complete

    // ---- Coarse histogram from registers ----
    #pragma unroll
    for (int j = 0; j < RPT; j++)
        if (t + j * 512 < n)
            atomicAdd(&shist[fflip(v[j].x) >> 20], 1);
    for (int i = 512 * RPT + t; i < n; i += 512)      // rare overflow
        atomicAdd(&shist[fflip(cd[i].x) >> 20], 1);
    __syncthreads();

    cut_scan512x(shist, s_wtot, &s_cb, &s_ab, KK, t);
    __syncthreads();
    const int cb = s_cb, ab = s_ab;

    // ---- Refine: histogram of bits [8:20) inside the cut bin ----
    {
        int4* h4 = (int4*)shist;
        h4[t]       = make_int4(0, 0, 0, 0);
        h4[t + 512] = make_int4(0, 0, 0, 0);
    }
    __syncthreads();
    #pragma unroll
    for (int j = 0; j < RPT; j++) {
        if (t + j * 512 < n) {
            unsigned f = fflip(v[j].x);
            if ((int)(f >> 20) == cb) atomicAdd(&shist[(f >> 8) & 0xFFFu], 1);
        }
    }
    for (int i = 512 * RPT + t; i < n; i += 512) {    // rare overflow
        unsigned f = fflip(cd[i].x);
        if ((int)(f >> 20) == cb) atomicAdd(&shist[(f >> 8) & 0xFFFu], 1);
    }
    __syncthreads();
    cut_scan512x(shist, s_wtot, &s_rb, &s_du, KK - ab, t);
    __syncthreads();
    const unsigned thr = ((unsigned)cb << 20) | ((unsigned)s_rb << 8);

    // ---- Collect survivors from registers (C ~ 110-200) ----
    #pragma unroll
    for (int j = 0; j < RPT; j++) {
        if (t + j * 512 < n && fflip(v[j].x) >= thr) {
            int pos = atomicAdd(&s_count, 1);
            if (pos < CAP) { s_d[pos] = v[j].x; s_i[pos] = __float_as_int(v[j].y); }
        }
    }
    for (int i = 512 * RPT + t; i < n; i += 512) {    // rare overflow
        float2 vv = cd[i];
        if (fflip(vv.x) >= thr) {
            int pos = atomicAdd(&s_count, 1);
            if (pos < CAP) { s_d[pos] = vv.x; s_i[pos] = __float_as_int(vv.y); }
        }
    }
    __syncthreads();

    const int C = min(s_count, CAP);

    // ---- Exact p in place, then exact stable rank: p desc, idx asc ----
    for (int e = t; e < C; e += 512) s_d[e] = prob_from_d(s_d[e]);
    __syncthreads();

    for (int e = t; e < C; e += 512) {
        const float p  = s_d[e];
        const int   id = s_i[e];
        int rank = 0;
        for (int j = 0; j < C; j++) {
            float pj = s_d[j];
            rank += (pj > p) || (pj == p && s_i[j] < id);
        }
        if (rank < KK) {
            int ww = id % WW;
            int hh = id / WW;
            float xc = (float)ww * 4.0f + 1.5f;
            float yc = (float)hh * 4.0f + 1.5f;
            float* o = out + ((size_t)b * KK + rank) * 5;
            o[0] = xc - 10.0f;
            o[1] = yc - 10.0f;
            o[2] = xc + 10.0f;
            o[3] = yc + 10.0f;
            o[4] = p;
        }
    }
}

// ---------------------------------------------------------------------------
extern "C" void kernel_launch(void* const* d_in, const int* in_sizes, int n_in,
                              void* d_out, int out_size) {
    const float* in = (const float*)d_in[0];
    float* out = (float*)d_out;

    dim3 grid(1, NBY, BB);                    // (1, 45, 16) = 720 blocks
    detect_kernel<<<grid, NT>>>(in);

    select_kernel<<<BB, 512>>>(out);
}

// round 16
// speedup vs baseline: 1.7419x; 1.0934x over previous
#include <cuda_runtime.h>
#include <math.h>
#include <stdint.h>

// FootAndBall ball-detection post-process — two kernels.
//  in : [16, 2, 540, 960] fp32 logits
//  out: [16, 100, 5] fp32 (x1,y1,x2,y2,score), score desc (idx asc on ties).
//
//  K1 detect : d = x1-x0 (NMS on d == NMS on softmax prob, monotone).
//    Streaming float4 NMS with GROUPS OF 2 rows (double-buffered): halves the
//    register staging (8 float4 vs 16) so 4 blocks/SM fit the register file,
//    and grid (1,30,16)=480 blocks runs in ONE wave (R10-R15 used 720 blocks
//    at 2-3 blocks/SM -> 2-3 waves; suspected cause of detect's 34us vs its
//    ~15us single-wave estimate). Warp-aggregated queue emission; deferred
//    histogram; TWO-LEVEL block-local top-100 cut (24-bit threshold) filters
//    to ~110/block before ONE contiguous per-batch flush. Queue overflow
//    falls back to direct unfiltered append (superset -> still correct).
//  K2 select : register-burst select with the same two-level cut (C ~ 150),
//    exact (p desc, idx asc) rank, box write, counter reset. (unchanged)
//  __device__ globals start zero-initialized; K2 restores zeros.

#define BB   16
#define HH   540
#define WW   960
#define HWSZ (HH * WW)
#define KK   100

#define NT    256                 // detect threads per block (8 warps)
#define RPB   18                  // rows per block; 540 = 30 * 18
#define NBY   30                  // blocks per batch
#define QC    2304                // block smem queue entries (18 KB)
#define HB    4096                // histogram bins (12 bits per level)
#define CAP   2048                // select survivor capacity (expected ~150)
#define CAPG  65536               // per-batch global candidate capacity
#define RPT   16                  // select: candidates per thread (512*16=8192)

__device__ int    g_cnt [BB];
__device__ float2 g_cand[BB][CAPG];

// ---------------------------------------------------------------------------
// Exact softmax channel-1 prob from d = fl(x1-x0). Matches jax.nn.softmax:
// one exp arg is exactly 0 and fl(x0-x1) == -d exactly. (rel_err ~1e-12.)
// ---------------------------------------------------------------------------
__device__ __forceinline__ float prob_from_d(float d) {
#ifdef __FAST_MATH__
    double dd = (double)d;
    double p = (d >= 0.0f) ? (1.0 / (exp(-dd) + 1.0))
                           : (exp(dd) / (exp(dd) + 1.0));
    return (float)p;
#else
    if (d >= 0.0f) { float e0 = expf(-d); return 1.0f / (e0 + 1.0f); }
    else           { float e1 = expf(d);  return e1 / (1.0f + e1);  }
#endif
}

// Order-preserving bit flip: float compare == unsigned compare after flip.
__device__ __forceinline__ unsigned fflip(float f) {
    unsigned u = __float_as_uint(f);
    return u ^ (((unsigned)((int)u >> 31)) | 0x80000000u);
}

// ---------------------------------------------------------------------------
// Log-parallel cut over a 4096-bin smem histogram (256 threads).
// Finds smallest bin c with count(bin >= c) >= K; writes *s_cutbin = c and
// *s_above = count(bin > c). If total < K, leaves both untouched (caller
// pre-zeroes -> keep-everything fallback).
// ---------------------------------------------------------------------------
__device__ __forceinline__ void cut_scan256x(const int* __restrict__ hist,
                                             int* __restrict__ s_wtot,
                                             int* __restrict__ s_cutbin,
                                             int* __restrict__ s_above,
                                             int K, int t) {
    const int lane = t & 31;
    const int w    = t >> 5;
    const int seg  = 255 - t;                // descending bin order
    int val = 0;
    const int4* h4 = (const int4*)(hist + seg * 16);
    #pragma unroll
    for (int j = 0; j < 4; j++) { int4 a = h4[j]; val += a.x + a.y + a.z + a.w; }

    int incl = val;
    #pragma unroll
    for (int sh = 1; sh < 32; sh <<= 1) {
        int n = __shfl_up_sync(0xffffffffu, incl, sh);
        if (lane >= sh) incl += n;
    }
    if (lane == 31) s_wtot[w] = incl;
    __syncthreads();
    if (t < 8) {
        int v = s_wtot[t];
        int inc = v;
        #pragma unroll
        for (int sh = 1; sh < 8; sh <<= 1) {
            int n = __shfl_up_sync(0x000000ffu, inc, sh);
            if (t >= sh) inc += n;
        }
        s_wtot[t] = inc - v;
    }
    __syncthreads();
    int excl = incl - val + s_wtot[w];       // count strictly above seg
    if (excl < K && excl + val >= K) {       // unique boundary thread
        int above = excl;
        int cut = seg * 16;
        #pragma unroll
        for (int c = seg * 16 + 15; c >= seg * 16; c--) {
            int hv = hist[c];
            if (above + hv >= K) { cut = c; break; }
            above += hv;
        }
        *s_cutbin = cut;
        *s_above  = above;
    }
}

// 512-thread variant (8 bins per thread) for the select kernel.
__device__ __forceinline__ void cut_scan512x(const int* __restrict__ hist,
                                             int* __restrict__ s_wtot,
                                             int* __restrict__ s_cutbin,
                                             int* __restrict__ s_above,
                                             int K, int t) {
    const int lane = t & 31;
    const int w    = t >> 5;
    const int seg  = 511 - t;
    int val = 0;
    const int4* h4 = (const int4*)(hist + seg * 8);
    #pragma unroll
    for (int j = 0; j < 2; j++) { int4 a = h4[j]; val += a.x + a.y + a.z + a.w; }

    int incl = val;
    #pragma unroll
    for (int sh = 1; sh < 32; sh <<= 1) {
        int n = __shfl_up_sync(0xffffffffu, incl, sh);
        if (lane >= sh) incl += n;
    }
    if (lane == 31) s_wtot[w] = incl;
    __syncthreads();
    if (t < 16) {
        int v = s_wtot[t];
        int inc = v;
        #pragma unroll
        for (int sh = 1; sh < 16; sh <<= 1) {
            int n = __shfl_up_sync(0x0000ffffu, inc, sh);
            if (t >= sh) inc += n;
        }
        s_wtot[t] = inc - v;
    }
    __syncthreads();
    int excl = incl - val + s_wtot[w];
    if (excl < K && excl + val >= K) {
        int above = excl;
        int cut = seg * 8;
        #pragma unroll
        for (int c = seg * 8 + 7; c >= seg * 8; c--) {
            int hv = hist[c];
            if (above + hv >= K) { cut = c; break; }
            above += hv;
        }
        *s_cutbin = cut;
        *s_above  = above;
    }
}

// ---------------------------------------------------------------------------
// K1: streaming NMS (groups of 2, double buffered) + warp-aggregated emit +
// two-level cut + filtered flush. Grid (1, 30, 16), block 256.
// ---------------------------------------------------------------------------
__global__ __launch_bounds__(NT) void detect_kernel(const float* __restrict__ in) {
    __shared__ __align__(16) int shist[HB];  // 16 KB
    __shared__ float2 s_q[QC];               // 18 KB
    __shared__ int    s_wtot[8];
    __shared__ int    s_cb, s_ab, s_rb, s_du;
    __shared__ int    s_qcnt, s_keep, s_gbase;

    const int b    = blockIdx.z;
    const int by   = blockIdx.y;
    const int tid  = threadIdx.x;
    const int w    = tid >> 5;
    const int lane = tid & 31;

    const int  c0     = w * 120 - 4 + 4 * lane;          // lane's first column
    const bool colok  = ((unsigned)c0 < (unsigned)WW);
    const int  cc     = colok ? c0 : 0;                  // clamped load column
    const bool laneok = (lane >= 1) && (lane <= 30);
    const unsigned lmask = (1u << lane) - 1u;
    const int  r0     = by * RPB;

    if (tid == 0) { s_qcnt = 0; s_keep = 0; s_cb = 0; s_ab = 0; s_rb = 0; s_du = 0; }
    __syncthreads();

    const float* __restrict__ p0 = in + (size_t)b * 2 * HWSZ;
    const float* __restrict__ p1 = p0 + HWSZ;
    int*    __restrict__ gctr = &g_cnt[b];
    float2* __restrict__ gcd  = g_cand[b];

    #define LDROW(R, A, Bv) {                                                  \
        int _rr = (R) < 0 ? 0 : ((R) >= HH ? HH - 1 : (R));                    \
        size_t _o = (size_t)_rr * WW + cc;                                     \
        A  = __ldg(reinterpret_cast<const float4*>(p0 + _o));                  \
        Bv = __ldg(reinterpret_cast<const float4*>(p1 + _o)); }

    #define LOADG(BUF, BASE) {                                                 \
        LDROW((BASE),     sa[BUF][0], sb[BUF][0])                              \
        LDROW((BASE) + 1, sa[BUF][1], sb[BUF][1]) }

    #define CVT(A, Bv, R, D) {                                                 \
        if (colok && ((unsigned)(R) < (unsigned)HH))                            \
            D = make_float4(Bv.x - A.x, Bv.y - A.y, Bv.z - A.z, Bv.w - A.w);    \
        else                                                                    \
            D = make_float4(-INFINITY, -INFINITY, -INFINITY, -INFINITY); }

    #define H3MAX4(D, HM) {                                                    \
        float _dl = __shfl_up_sync(0xffffffffu, (D).w, 1);                      \
        float _dr = __shfl_down_sync(0xffffffffu, (D).x, 1);                    \
        (HM).x = fmaxf(_dl,   fmaxf((D).x, (D).y));                             \
        (HM).y = fmaxf((D).x, fmaxf((D).y, (D).z));                             \
        (HM).z = fmaxf((D).y, fmaxf((D).z, (D).w));                             \
        (HM).w = fmaxf((D).z, fmaxf((D).w, _dr)); }

    // Queue put with global overflow fallback (unfiltered -> superset, OK).
    #define QPUT(P, V, I) {                                                    \
        float2 _v = make_float2(V, __int_as_float(I));                          \
        if ((P) < QC) s_q[P] = _v;                                              \
        else { int _g = atomicAdd(gctr, 1); if (_g < CAPG) gcd[_g] = _v; } }

    // Warp-aggregated emission: 4 ballots, ONE s_qcnt atomic per (warp,row).
    #define EMITROW(DC, HA, HBv, HC, R) {                                      \
        float _m0 = fmaxf((HA).x, fmaxf((HBv).x, (HC).x));                     \
        float _m1 = fmaxf((HA).y, fmaxf((HBv).y, (HC).y));                     \
        float _m2 = fmaxf((HA).z, fmaxf((HBv).z, (HC).z));                     \
        float _m3 = fmaxf((HA).w, fmaxf((HBv).w, (HC).w));                     \
        bool _k0 = laneok && ((DC).x >= _m0);                                  \
        bool _k1 = laneok && ((DC).y >= _m1);                                  \
        bool _k2 = laneok && ((DC).z >= _m2);                                  \
        bool _k3 = laneok && ((DC).w >= _m3);                                  \
        unsigned _b0 = __ballot_sync(0xffffffffu, _k0);                        \
        unsigned _b1 = __ballot_sync(0xffffffffu, _k1);                        \
        unsigned _b2 = __ballot_sync(0xffffffffu, _k2);                        \
        unsigned _b3 = __ballot_sync(0xffffffffu, _k3);                        \
        int _n0 = __popc(_b0), _n1 = __popc(_b1);                              \
        int _n2 = __popc(_b2), _n3 = __popc(_b3);                              \
        int _nc = _n0 + _n1 + _n2 + _n3;                                       \
        if (_nc) {                                                             \
            int _base = 0;                                                     \
            if (lane == 0) _base = atomicAdd(&s_qcnt, _nc);                    \
            _base = __shfl_sync(0xffffffffu, _base, 0);                        \
            int _ib = (R) * WW + c0;                                           \
            if (_k0) QPUT(_base + __popc(_b0 & lmask), (DC).x, _ib)            \
            if (_k1) QPUT(_base + _n0 + __popc(_b1 & lmask), (DC).y, _ib + 1)  \
            if (_k2) QPUT(_base + _n0 + _n1 + __popc(_b2 & lmask),             \
                          (DC).z, _ib + 2)                                     \
            if (_k3) QPUT(_base + _n0 + _n1 + _n2 + __popc(_b3 & lmask),       \
                          (DC).w, _ib + 3)                                     \
        } }

    // --- Streaming NMS: 18 rows as 9 groups of 2, double-buffered loads ----
    {
        float4 sa[2][2], sb[2][2];
        float4 hmA, hmB, dB;
        {
            float4 xa, xb, ya, yb, dm;
            LDROW(r0 - 1, xa, xb)
            LDROW(r0, ya, yb)
            LOADG(0, r0 + 1)                 // rows r0+1, r0+2 (early)
            LOADG(1, r0 + 3)                 // rows r0+3, r0+4 (early)
            CVT(xa, xb, r0 - 1, dm)  H3MAX4(dm, hmA)
            CVT(ya, yb, r0, dB)      H3MAX4(dB, hmB)
        }
        #pragma unroll
        for (int k = 0; k < 9; k++) {
            const int buf = k & 1;
            float4 d1, d2, h1, h2;
            CVT(sa[buf][0], sb[buf][0], r0 + 2 * k + 1, d1)  H3MAX4(d1, h1)
            CVT(sa[buf][1], sb[buf][1], r0 + 2 * k + 2, d2)  H3MAX4(d2, h2)
            if (k < 7) LOADG(buf, r0 + 2 * k + 5)   // refill for iter k+2
            EMITROW(dB, hmA, hmB, h1, r0 + 2 * k)
            EMITROW(d1, hmB, h1, h2, r0 + 2 * k + 1)
            hmA = h1; hmB = h2; dB = d2;
        }
    }
    __syncthreads();

    const int qn = min(s_qcnt, QC);

    // --- Deferred histogram over queue members ------------------------------
    #pragma unroll
    for (int i = tid; i < HB; i += NT) shist[i] = 0;
    __syncthreads();
    for (int i = tid; i < qn; i += NT)
        atomicAdd(&shist[fflip(s_q[i].x) >> 20], 1);
    __syncthreads();

    // --- Two-level block-local top-100 cut ----------------------------------
    cut_scan256x(shist, s_wtot, &s_cb, &s_ab, KK, tid);
    __syncthreads();
    const int cb = s_cb, ab = s_ab;

    #pragma unroll
    for (int i = tid; i < HB; i += NT) shist[i] = 0;   // re-zero for refine
    __syncthreads();
    for (int i = tid; i < qn; i += NT) {
        unsigned f = fflip(s_q[i].x);
        if ((int)(f >> 20) == cb) atomicAdd(&shist[(f >> 8) & 0xFFFu], 1);
    }
    __syncthreads();
    cut_scan256x(shist, s_wtot, &s_rb, &s_du, KK - ab, tid);
    __syncthreads();
    const unsigned bthr = ((unsigned)cb << 20) | ((unsigned)s_rb << 8);

    // --- Filtered contiguous flush of the queue -----------------------------
    int cnt = 0;
    for (int i = tid; i < qn; i += NT)
        cnt += (fflip(s_q[i].x) >= bthr);
    if (cnt) atomicAdd(&s_keep, cnt);
    __syncthreads();
    if (tid == 0) {
        s_gbase = (s_keep > 0) ? atomicAdd(gctr, s_keep) : 0;
        s_keep = 0;
    }
    __syncthreads();
    for (int i = tid; i < qn; i += NT) {
        float2 v = s_q[i];
        if (fflip(v.x) >= bthr) {
            int p = s_gbase + atomicAdd(&s_keep, 1);
            if (p < CAPG) gcd[p] = v;
        }
    }
}

// ---------------------------------------------------------------------------
// K2: register-burst per-batch top-100 with two-level cut. Grid BB, block 512.
// (Unchanged.)
// ---------------------------------------------------------------------------
__global__ __launch_bounds__(512) void select_kernel(float* __restrict__ out) {
    __shared__ __align__(16) int shist[HB];  // 16 KB
    __shared__ int      s_wtot[16];
    __shared__ int      s_cb, s_ab, s_rb, s_du;
    __shared__ int      s_count;
    __shared__ float    s_d[CAP];            // 8 KB (d, overwritten by p)
    __shared__ int      s_i[CAP];            // 8 KB

    const int b = blockIdx.x;
    const int t = threadIdx.x;

    {   // vectorized smem hist zero
        int4* h4 = (int4*)shist;
        h4[t]       = make_int4(0, 0, 0, 0);
        h4[t + 512] = make_int4(0, 0, 0, 0);
    }
    if (t == 0) { s_cb = 0; s_ab = 0; s_rb = 0; s_du = 0; s_count = 0; }

    const int n = min(g_cnt[b], CAPG);
    if (t == 0) g_cnt[b] = 0;               // reset for next graph replay
    const float2* __restrict__ cd = g_cand[b];

    // ---- One unpredicated load burst ----
    float2 v[RPT];
    #pragma unroll
    for (int j = 0; j < RPT; j++) {
        int idx = t + j * 512;
        int ii  = (idx < n) ? idx : 0;       // clamp keeps the load legal
        v[j] = __ldg(cd + ii);
    }
    __syncthreads();                          // hist zero complete

    // ---- Coarse histogram from registers ----
    #pragma unroll
    for (int j = 0; j < RPT; j++)
        if (t + j * 512 < n)
            atomicAdd(&shist[fflip(v[j].x) >> 20], 1);
    for (int i = 512 * RPT + t; i < n; i += 512)      // rare overflow
        atomicAdd(&shist[fflip(cd[i].x) >> 20], 1);
    __syncthreads();

    cut_scan512x(shist, s_wtot, &s_cb, &s_ab, KK, t);
    __syncthreads();
    const int cb = s_cb, ab = s_ab;

    // ---- Refine: histogram of bits [8:20) inside the cut bin ----
    {
        int4* h4 = (int4*)shist;
        h4[t]       = make_int4(0, 0, 0, 0);
        h4[t + 512] = make_int4(0, 0, 0, 0);
    }
    __syncthreads();
    #pragma unroll
    for (int j = 0; j < RPT; j++) {
        if (t + j * 512 < n) {
            unsigned f = fflip(v[j].x);
            if ((int)(f >> 20) == cb) atomicAdd(&shist[(f >> 8) & 0xFFFu], 1);
        }
    }
    for (int i = 512 * RPT + t; i < n; i += 512) {    // rare overflow
        unsigned f = fflip(cd[i].x);
        if ((int)(f >> 20) == cb) atomicAdd(&shist[(f >> 8) & 0xFFFu], 1);
    }
    __syncthreads();
    cut_scan512x(shist, s_wtot, &s_rb, &s_du, KK - ab, t);
    __syncthreads();
    const unsigned thr = ((unsigned)cb << 20) | ((unsigned)s_rb << 8);

    // ---- Collect survivors from registers (C ~ 110-200) ----
    #pragma unroll
    for (int j = 0; j < RPT; j++) {
        if (t + j * 512 < n && fflip(v[j].x) >= thr) {
            int pos = atomicAdd(&s_count, 1);
            if (pos < CAP) { s_d[pos] = v[j].x; s_i[pos] = __float_as_int(v[j].y); }
        }
    }
    for (int i = 512 * RPT + t; i < n; i += 512) {    // rare overflow
        float2 vv = cd[i];
        if (fflip(vv.x) >= thr) {
            int pos = atomicAdd(&s_count, 1);
            if (pos < CAP) { s_d[pos] = vv.x; s_i[pos] = __float_as_int(vv.y); }
        }
    }
    __syncthreads();

    const int C = min(s_count, CAP);

    // ---- Exact p in place, then exact stable rank: p desc, idx asc ----
    for (int e = t; e < C; e += 512) s_d[e] = prob_from_d(s_d[e]);
    __syncthreads();

    for (int e = t; e < C; e += 512) {
        const float p  = s_d[e];
        const int   id = s_i[e];
        int rank = 0;
        for (int j = 0; j < C; j++) {
            float pj = s_d[j];
            rank += (pj > p) || (pj == p && s_i[j] < id);
        }
        if (rank < KK) {
            int ww = id % WW;
            int hh = id / WW;
            float xc = (float)ww * 4.0f + 1.5f;
            float yc = (float)hh * 4.0f + 1.5f;
            float* o = out + ((size_t)b * KK + rank) * 5;
            o[0] = xc - 10.0f;
            o[1] = yc - 10.0f;
            o[2] = xc + 10.0f;
            o[3] = yc + 10.0f;
            o[4] = p;
        }
    }
}

// ---------------------------------------------------------------------------
extern "C" void kernel_launch(void* const* d_in, const int* in_sizes, int n_in,
                              void* d_out, int out_size) {
    const float* in = (const float*)d_in[0];
    float* out = (float*)d_out;

    dim3 grid(1, NBY, BB);                    // (1, 30, 16) = 480 blocks
    detect_kernel<<<grid, NT>>>(in);

    select_kernel<<<BB, 512>>>(out);
}